// round 10
// baseline (speedup 1.0000x reference)
#include <cuda_runtime.h>
#include <cuda_bf16.h>
#include <cstddef>

// Problem constants
#define BB 2
#define NN 2048
#define DD 256
#define HH 8
#define HDD 32
#define DFF 1024
#define MROWS (BB*NN)          // 4096
static __device__ __constant__ float kScale = 5.656854249492381f; // sqrt(32), source MULTIPLIES

// ---------------- scratch (static device globals; no allocation) --------------
__device__ float g_qkv   [(size_t)BB*NN*3*DD];   // [B,N,768]
__device__ float g_att   [(size_t)BB*NN*DD];     // attention output (pre-proj)
__device__ float g_res   [(size_t)BB*NN*DD];     // proj + bias + x (pre-LN)
__device__ float g_net   [(size_t)BB*NN*DD];     // layernorm output
__device__ float g_hidden[(size_t)BB*NN*DFF];    // fc1 output

// ============================= GEMM =========================================
// C[M,N] = A[M,K] @ W[K,N]  (+ bias[N])  (+ res[M,N])
// Block tile 128x64, BK=32, 256 threads, 8x4 register micro-tile.
template<bool BIAS, bool RES>
__global__ __launch_bounds__(256) void gemm_kernel(
    const float* __restrict__ A, const float* __restrict__ W,
    const float* __restrict__ bias, const float* __restrict__ res,
    float* __restrict__ C, int M, int N, int K)
{
    constexpr int BM = 128, BN = 64, BK = 32;
    constexpr int PAD = 4;                       // bank-conflict mitigation for transposed store
    __shared__ float As[BK][BM + PAD];           // As[k][m]
    __shared__ float Bs[BK][BN];                 // Bs[k][n]

    const int tid = threadIdx.x;
    const int bm  = blockIdx.y;
    const int bn  = blockIdx.x;
    const int tx  = tid & 15;                    // 16 col-groups (TN=4)
    const int ty  = tid >> 4;                    // 16 row-groups (TM=8)

    float acc[8][4];
    #pragma unroll
    for (int i = 0; i < 8; i++)
        #pragma unroll
        for (int j = 0; j < 4; j++) acc[i][j] = 0.f;

    const int ar = tid >> 3;                     // 0..31 (A row within pass)
    const int ac = (tid & 7) * 4;                // 0..28 (A col, float4)
    const int br = tid >> 4;                     // 0..15 (B row within pass)
    const int bc = (tid & 15) * 4;               // 0..60 (B col, float4)

    const float* Ablk = A + (size_t)(bm * BM) * K;
    const float* Wblk = W + (size_t)bn * BN;

    for (int kt = 0; kt < K; kt += BK) {
        // ---- load A tile (128 x 32), store transposed ----
        #pragma unroll
        for (int p = 0; p < 4; p++) {
            int r = ar + p * 32;
            float4 v = *(const float4*)(Ablk + (size_t)r * K + kt + ac);
            As[ac + 0][r] = v.x; As[ac + 1][r] = v.y;
            As[ac + 2][r] = v.z; As[ac + 3][r] = v.w;
        }
        // ---- load B tile (32 x 64) ----
        #pragma unroll
        for (int p = 0; p < 2; p++) {
            int r = br + p * 16;
            *(float4*)&Bs[r][bc] = *(const float4*)(Wblk + (size_t)(kt + r) * N + bc);
        }
        __syncthreads();

        #pragma unroll
        for (int k = 0; k < BK; k++) {
            float4 b4 = *(const float4*)&Bs[k][tx * 4];
            float4 a0 = *(const float4*)&As[k][ty * 8];
            float4 a1 = *(const float4*)&As[k][ty * 8 + 4];
            float a[8] = {a0.x, a0.y, a0.z, a0.w, a1.x, a1.y, a1.z, a1.w};
            float bb[4] = {b4.x, b4.y, b4.z, b4.w};
            #pragma unroll
            for (int i = 0; i < 8; i++)
                #pragma unroll
                for (int j = 0; j < 4; j++)
                    acc[i][j] += a[i] * bb[j];
        }
        __syncthreads();
    }

    // ---- epilogue ----
    const int col = bn * BN + tx * 4;
    float4 bv = make_float4(0.f, 0.f, 0.f, 0.f);
    if (BIAS) bv = *(const float4*)(bias + col);
    #pragma unroll
    for (int i = 0; i < 8; i++) {
        int row = bm * BM + ty * 8 + i;
        float4 o;
        o.x = acc[i][0] + bv.x; o.y = acc[i][1] + bv.y;
        o.z = acc[i][2] + bv.z; o.w = acc[i][3] + bv.w;
        if (RES) {
            float4 r = *(const float4*)(res + (size_t)row * N + col);
            o.x += r.x; o.y += r.y; o.z += r.z; o.w += r.w;
        }
        *(float4*)(C + (size_t)row * N + col) = o;
    }
}

// ============================ Attention ======================================
// Flash-style, fp32. 1 thread = 1 query row. Block: 128 threads = 128 queries.
// Grid: (N/128, H, B). K/V tiles of 32 keys in shared memory.
__global__ __launch_bounds__(128) void attn_kernel(
    const float* __restrict__ qkv, float* __restrict__ out)
{
    const int tid  = threadIdx.x;
    const int h    = blockIdx.y;
    const int b    = blockIdx.z;
    const int qrow = blockIdx.x * 128 + tid;

    const float* base = qkv + (size_t)b * NN * (3 * DD) + h * HDD;
    const float* Kb = base + DD;        // k at offset 256 in last dim
    const float* Vb = base + 2 * DD;    // v at offset 512

    __shared__ float4 Ks[32][8];
    __shared__ float4 Vs[32][8];

    float q[32], acc[32];
    {
        const float* qp = base + (size_t)qrow * (3 * DD);
        const float sc = kScale;
        #pragma unroll
        for (int i = 0; i < 8; i++) {
            float4 t = *(const float4*)(qp + i * 4);
            q[4*i+0] = t.x * sc; q[4*i+1] = t.y * sc;
            q[4*i+2] = t.z * sc; q[4*i+3] = t.w * sc;
        }
    }
    #pragma unroll
    for (int d = 0; d < 32; d++) acc[d] = 0.f;
    float m = -1e30f, l = 0.f;

    const int r0 = tid >> 3,        c0 = (tid & 7) * 4;
    const int r1 = (tid + 128) >> 3, c1 = (tid & 7) * 4;   // second pass, rows 16..31

    for (int kb = 0; kb < NN; kb += 32) {
        // ---- load 32 keys + 32 values (each 32 floats) ----
        Ks[r0][c0 >> 2] = *(const float4*)(Kb + (size_t)(kb + r0) * (3 * DD) + c0);
        Ks[r1][c1 >> 2] = *(const float4*)(Kb + (size_t)(kb + r1) * (3 * DD) + c1);
        Vs[r0][c0 >> 2] = *(const float4*)(Vb + (size_t)(kb + r0) * (3 * DD) + c0);
        Vs[r1][c1 >> 2] = *(const float4*)(Vb + (size_t)(kb + r1) * (3 * DD) + c1);
        __syncthreads();

        // ---- scores: s[j] = (q*scale) . k_j ----
        float s[32];
        #pragma unroll
        for (int j = 0; j < 32; j++) {
            float a0 = 0.f, a1 = 0.f, a2 = 0.f, a3 = 0.f;
            #pragma unroll
            for (int i = 0; i < 8; i++) {
                float4 kv = Ks[j][i];
                a0 += q[4*i+0] * kv.x; a1 += q[4*i+1] * kv.y;
                a2 += q[4*i+2] * kv.z; a3 += q[4*i+3] * kv.w;
            }
            s[j] = (a0 + a1) + (a2 + a3);
        }

        // ---- online softmax, rescale once per tile ----
        float tmax = s[0];
        #pragma unroll
        for (int j = 1; j < 32; j++) tmax = fmaxf(tmax, s[j]);
        float mnew  = fmaxf(m, tmax);
        float alpha = __expf(m - mnew);
        l *= alpha;
        #pragma unroll
        for (int d = 0; d < 32; d++) acc[d] *= alpha;

        #pragma unroll
        for (int j = 0; j < 32; j++) {
            float p = __expf(s[j] - mnew);
            l += p;
            #pragma unroll
            for (int i = 0; i < 8; i++) {
                float4 vv = Vs[j][i];
                acc[4*i+0] += p * vv.x; acc[4*i+1] += p * vv.y;
                acc[4*i+2] += p * vv.z; acc[4*i+3] += p * vv.w;
            }
        }
        m = mnew;
        __syncthreads();
    }

    const float inv = 1.f / l;
    float* op = out + ((size_t)(b * NN + qrow)) * DD + h * HDD;
    #pragma unroll
    for (int i = 0; i < 8; i++) {
        float4 o;
        o.x = acc[4*i+0] * inv; o.y = acc[4*i+1] * inv;
        o.z = acc[4*i+2] * inv; o.w = acc[4*i+3] * inv;
        *(float4*)(op + 4 * i) = o;
    }
}

// ============================ LayerNorm ======================================
// One block per row (D=256), 256 threads.
__global__ __launch_bounds__(256) void ln_kernel(
    const float* __restrict__ in, const float* __restrict__ gamma,
    const float* __restrict__ beta, float* __restrict__ out)
{
    __shared__ float red[8];
    const int row = blockIdx.x;
    const int tid = threadIdx.x;

    float v = in[(size_t)row * DD + tid];

    float s = v;
    #pragma unroll
    for (int o = 16; o; o >>= 1) s += __shfl_xor_sync(0xffffffffu, s, o);
    if ((tid & 31) == 0) red[tid >> 5] = s;
    __syncthreads();
    float tot = 0.f;
    #pragma unroll
    for (int i = 0; i < 8; i++) tot += red[i];
    const float mu = tot * (1.f / DD);

    float d = v - mu;
    float sq = d * d;
    #pragma unroll
    for (int o = 16; o; o >>= 1) sq += __shfl_xor_sync(0xffffffffu, sq, o);
    __syncthreads();
    if ((tid & 31) == 0) red[tid >> 5] = sq;
    __syncthreads();
    float var = 0.f;
    #pragma unroll
    for (int i = 0; i < 8; i++) var += red[i];
    var *= (1.f / DD);

    out[(size_t)row * DD + tid] = d * rsqrtf(var + 1e-5f) * gamma[tid] + beta[tid];
}

// ============================ launch =========================================
extern "C" void kernel_launch(void* const* d_in, const int* in_sizes, int n_in,
                              void* d_out, int out_size)
{
    const float* x      = (const float*)d_in[0];
    const float* qkv_w  = (const float*)d_in[1];
    const float* proj_w = (const float*)d_in[2];
    const float* proj_b = (const float*)d_in[3];
    const float* fc1_w  = (const float*)d_in[4];
    const float* fc1_b  = (const float*)d_in[5];
    const float* fc2_w  = (const float*)d_in[6];
    const float* fc2_b  = (const float*)d_in[7];
    const float* ln1_g  = (const float*)d_in[8];
    const float* ln1_b  = (const float*)d_in[9];
    float* out = (float*)d_out;

    float *qkvp, *attp, *resp, *netp, *hidp;
    cudaGetSymbolAddress((void**)&qkvp, g_qkv);
    cudaGetSymbolAddress((void**)&attp, g_att);
    cudaGetSymbolAddress((void**)&resp, g_res);
    cudaGetSymbolAddress((void**)&netp, g_net);
    cudaGetSymbolAddress((void**)&hidp, g_hidden);

    // 1) qkv = x @ qkv_w               [4096,768] = [4096,256]@[256,768]
    gemm_kernel<false, false><<<dim3(768 / 64, MROWS / 128), 256>>>(
        x, qkv_w, nullptr, nullptr, qkvp, MROWS, 3 * DD, DD);

    // 2) attention (fused flash, per head)
    attn_kernel<<<dim3(NN / 128, HH, BB), 128>>>(qkvp, attp);

    // 3) res = att @ proj_w + proj_b + x
    gemm_kernel<true, true><<<dim3(DD / 64, MROWS / 128), 256>>>(
        attp, proj_w, proj_b, x, resp, MROWS, DD, DD);

    // 4) net = layernorm(res)
    ln_kernel<<<MROWS, 256>>>(resp, ln1_g, ln1_b, netp);

    // 5) hidden = net @ fc1_w + fc1_b   (NO activation per source)
    gemm_kernel<true, false><<<dim3(DFF / 64, MROWS / 128), 256>>>(
        netp, fc1_w, fc1_b, nullptr, hidp, MROWS, DFF, DD);

    // 6) out = hidden @ fc2_w + fc2_b + net
    gemm_kernel<true, true><<<dim3(DD / 64, MROWS / 128), 256>>>(
        hidp, fc2_w, fc2_b, netp, out, MROWS, DD, DFF);
}

// round 13
// speedup vs baseline: 1.0036x; 1.0036x over previous
#include <cuda_runtime.h>
#include <cuda_bf16.h>
#include <cstddef>

// Problem constants
#define BB 2
#define NN 2048
#define DD 256
#define HH 8
#define HDD 32
#define DFF 1024
#define MROWS (BB*NN)          // 4096
static __device__ __constant__ float kScale = 5.656854249492381f; // sqrt(32), source MULTIPLIES

// ---------------- scratch (static device globals; no allocation) --------------
__device__ float g_qkv   [(size_t)BB*NN*3*DD];   // [B,N,768]
__device__ float g_att   [(size_t)BB*NN*DD];     // attention output (pre-proj)
__device__ float g_res   [(size_t)BB*NN*DD];     // proj + bias + x (pre-LN)
__device__ float g_net   [(size_t)BB*NN*DD];     // layernorm output
__device__ float g_hidden[(size_t)BB*NN*DFF];    // fc1 output

// ============================= GEMM =========================================
// C[M,N] = A[M,K] @ W[K,N]  (+ bias[N])  (+ res[M,N])
// Block tile 128x64, BK=32, 256 threads, 8x4 register micro-tile.
template<bool BIAS, bool RES>
__global__ __launch_bounds__(256) void gemm_kernel(
    const float* __restrict__ A, const float* __restrict__ W,
    const float* __restrict__ bias, const float* __restrict__ res,
    float* __restrict__ C, int M, int N, int K)
{
    constexpr int BM = 128, BN = 64, BK = 32;
    constexpr int PAD = 4;                       // bank-conflict mitigation for transposed store
    __shared__ float As[BK][BM + PAD];           // As[k][m]
    __shared__ float Bs[BK][BN];                 // Bs[k][n]

    const int tid = threadIdx.x;
    const int bm  = blockIdx.y;
    const int bn  = blockIdx.x;
    const int tx  = tid & 15;                    // 16 col-groups (TN=4)
    const int ty  = tid >> 4;                    // 16 row-groups (TM=8)

    float acc[8][4];
    #pragma unroll
    for (int i = 0; i < 8; i++)
        #pragma unroll
        for (int j = 0; j < 4; j++) acc[i][j] = 0.f;

    const int ar = tid >> 3;                     // 0..31 (A row within pass)
    const int ac = (tid & 7) * 4;                // 0..28 (A col, float4)
    const int br = tid >> 4;                     // 0..15 (B row within pass)
    const int bc = (tid & 15) * 4;               // 0..60 (B col, float4)

    const float* Ablk = A + (size_t)(bm * BM) * K;
    const float* Wblk = W + (size_t)bn * BN;

    for (int kt = 0; kt < K; kt += BK) {
        // ---- load A tile (128 x 32), store transposed ----
        #pragma unroll
        for (int p = 0; p < 4; p++) {
            int r = ar + p * 32;
            float4 v = *(const float4*)(Ablk + (size_t)r * K + kt + ac);
            As[ac + 0][r] = v.x; As[ac + 1][r] = v.y;
            As[ac + 2][r] = v.z; As[ac + 3][r] = v.w;
        }
        // ---- load B tile (32 x 64) ----
        #pragma unroll
        for (int p = 0; p < 2; p++) {
            int r = br + p * 16;
            *(float4*)&Bs[r][bc] = *(const float4*)(Wblk + (size_t)(kt + r) * N + bc);
        }
        __syncthreads();

        #pragma unroll
        for (int k = 0; k < BK; k++) {
            float4 b4 = *(const float4*)&Bs[k][tx * 4];
            float4 a0 = *(const float4*)&As[k][ty * 8];
            float4 a1 = *(const float4*)&As[k][ty * 8 + 4];
            float a[8] = {a0.x, a0.y, a0.z, a0.w, a1.x, a1.y, a1.z, a1.w};
            float bb[4] = {b4.x, b4.y, b4.z, b4.w};
            #pragma unroll
            for (int i = 0; i < 8; i++)
                #pragma unroll
                for (int j = 0; j < 4; j++)
                    acc[i][j] += a[i] * bb[j];
        }
        __syncthreads();
    }

    // ---- epilogue ----
    const int col = bn * BN + tx * 4;
    float4 bv = make_float4(0.f, 0.f, 0.f, 0.f);
    if (BIAS) bv = *(const float4*)(bias + col);
    #pragma unroll
    for (int i = 0; i < 8; i++) {
        int row = bm * BM + ty * 8 + i;
        float4 o;
        o.x = acc[i][0] + bv.x; o.y = acc[i][1] + bv.y;
        o.z = acc[i][2] + bv.z; o.w = acc[i][3] + bv.w;
        if (RES) {
            float4 r = *(const float4*)(res + (size_t)row * N + col);
            o.x += r.x; o.y += r.y; o.z += r.z; o.w += r.w;
        }
        *(float4*)(C + (size_t)row * N + col) = o;
    }
}

// ============================ Attention ======================================
// Flash-style, fp32. 1 thread = 1 query row. Block: 128 threads = 128 queries.
// Grid: (N/128, H, B). K/V tiles of 32 keys in shared memory.
__global__ __launch_bounds__(128) void attn_kernel(
    const float* __restrict__ qkv, float* __restrict__ out)
{
    const int tid  = threadIdx.x;
    const int h    = blockIdx.y;
    const int b    = blockIdx.z;
    const int qrow = blockIdx.x * 128 + tid;

    const float* base = qkv + (size_t)b * NN * (3 * DD) + h * HDD;
    const float* Kb = base + DD;        // k at offset 256 in last dim
    const float* Vb = base + 2 * DD;    // v at offset 512

    __shared__ float4 Ks[32][8];
    __shared__ float4 Vs[32][8];

    float q[32], acc[32];
    {
        const float* qp = base + (size_t)qrow * (3 * DD);
        const float sc = kScale;
        #pragma unroll
        for (int i = 0; i < 8; i++) {
            float4 t = *(const float4*)(qp + i * 4);
            q[4*i+0] = t.x * sc; q[4*i+1] = t.y * sc;
            q[4*i+2] = t.z * sc; q[4*i+3] = t.w * sc;
        }
    }
    #pragma unroll
    for (int d = 0; d < 32; d++) acc[d] = 0.f;
    float m = -1e30f, l = 0.f;

    const int r0 = tid >> 3,        c0 = (tid & 7) * 4;
    const int r1 = (tid + 128) >> 3, c1 = (tid & 7) * 4;   // second pass, rows 16..31

    for (int kb = 0; kb < NN; kb += 32) {
        // ---- load 32 keys + 32 values (each 32 floats) ----
        Ks[r0][c0 >> 2] = *(const float4*)(Kb + (size_t)(kb + r0) * (3 * DD) + c0);
        Ks[r1][c1 >> 2] = *(const float4*)(Kb + (size_t)(kb + r1) * (3 * DD) + c1);
        Vs[r0][c0 >> 2] = *(const float4*)(Vb + (size_t)(kb + r0) * (3 * DD) + c0);
        Vs[r1][c1 >> 2] = *(const float4*)(Vb + (size_t)(kb + r1) * (3 * DD) + c1);
        __syncthreads();

        // ---- scores: s[j] = (q*scale) . k_j ----
        float s[32];
        #pragma unroll
        for (int j = 0; j < 32; j++) {
            float a0 = 0.f, a1 = 0.f, a2 = 0.f, a3 = 0.f;
            #pragma unroll
            for (int i = 0; i < 8; i++) {
                float4 kv = Ks[j][i];
                a0 += q[4*i+0] * kv.x; a1 += q[4*i+1] * kv.y;
                a2 += q[4*i+2] * kv.z; a3 += q[4*i+3] * kv.w;
            }
            s[j] = (a0 + a1) + (a2 + a3);
        }

        // ---- online softmax, rescale once per tile ----
        float tmax = s[0];
        #pragma unroll
        for (int j = 1; j < 32; j++) tmax = fmaxf(tmax, s[j]);
        float mnew  = fmaxf(m, tmax);
        float alpha = __expf(m - mnew);
        l *= alpha;
        #pragma unroll
        for (int d = 0; d < 32; d++) acc[d] *= alpha;

        #pragma unroll
        for (int j = 0; j < 32; j++) {
            float p = __expf(s[j] - mnew);
            l += p;
            #pragma unroll
            for (int i = 0; i < 8; i++) {
                float4 vv = Vs[j][i];
                acc[4*i+0] += p * vv.x; acc[4*i+1] += p * vv.y;
                acc[4*i+2] += p * vv.z; acc[4*i+3] += p * vv.w;
            }
        }
        m = mnew;
        __syncthreads();
    }

    const float inv = 1.f / l;
    float* op = out + ((size_t)(b * NN + qrow)) * DD + h * HDD;
    #pragma unroll
    for (int i = 0; i < 8; i++) {
        float4 o;
        o.x = acc[4*i+0] * inv; o.y = acc[4*i+1] * inv;
        o.z = acc[4*i+2] * inv; o.w = acc[4*i+3] * inv;
        *(float4*)(op + 4 * i) = o;
    }
}

// ============================ LayerNorm ======================================
// One block per row (D=256), 256 threads.
__global__ __launch_bounds__(256) void ln_kernel(
    const float* __restrict__ in, const float* __restrict__ gamma,
    const float* __restrict__ beta, float* __restrict__ out)
{
    __shared__ float red[8];
    const int row = blockIdx.x;
    const int tid = threadIdx.x;

    float v = in[(size_t)row * DD + tid];

    float s = v;
    #pragma unroll
    for (int o = 16; o; o >>= 1) s += __shfl_xor_sync(0xffffffffu, s, o);
    if ((tid & 31) == 0) red[tid >> 5] = s;
    __syncthreads();
    float tot = 0.f;
    #pragma unroll
    for (int i = 0; i < 8; i++) tot += red[i];
    const float mu = tot * (1.f / DD);

    float d = v - mu;
    float sq = d * d;
    #pragma unroll
    for (int o = 16; o; o >>= 1) sq += __shfl_xor_sync(0xffffffffu, sq, o);
    __syncthreads();
    if ((tid & 31) == 0) red[tid >> 5] = sq;
    __syncthreads();
    float var = 0.f;
    #pragma unroll
    for (int i = 0; i < 8; i++) var += red[i];
    var *= (1.f / DD);

    out[(size_t)row * DD + tid] = d * rsqrtf(var + 1e-5f) * gamma[tid] + beta[tid];
}

// ============================ launch =========================================
extern "C" void kernel_launch(void* const* d_in, const int* in_sizes, int n_in,
                              void* d_out, int out_size)
{
    const float* x      = (const float*)d_in[0];
    const float* qkv_w  = (const float*)d_in[1];
    const float* proj_w = (const float*)d_in[2];
    const float* proj_b = (const float*)d_in[3];
    const float* fc1_w  = (const float*)d_in[4];
    const float* fc1_b  = (const float*)d_in[5];
    const float* fc2_w  = (const float*)d_in[6];
    const float* fc2_b  = (const float*)d_in[7];
    const float* ln1_g  = (const float*)d_in[8];
    const float* ln1_b  = (const float*)d_in[9];
    float* out = (float*)d_out;

    float *qkvp, *attp, *resp, *netp, *hidp;
    cudaGetSymbolAddress((void**)&qkvp, g_qkv);
    cudaGetSymbolAddress((void**)&attp, g_att);
    cudaGetSymbolAddress((void**)&resp, g_res);
    cudaGetSymbolAddress((void**)&netp, g_net);
    cudaGetSymbolAddress((void**)&hidp, g_hidden);

    // 1) qkv = x @ qkv_w               [4096,768] = [4096,256]@[256,768]
    gemm_kernel<false, false><<<dim3(768 / 64, MROWS / 128), 256>>>(
        x, qkv_w, nullptr, nullptr, qkvp, MROWS, 3 * DD, DD);

    // 2) attention (fused flash, per head)
    attn_kernel<<<dim3(NN / 128, HH, BB), 128>>>(qkvp, attp);

    // 3) res = att @ proj_w + proj_b + x
    gemm_kernel<true, true><<<dim3(DD / 64, MROWS / 128), 256>>>(
        attp, proj_w, proj_b, x, resp, MROWS, DD, DD);

    // 4) net = layernorm(res)
    ln_kernel<<<MROWS, 256>>>(resp, ln1_g, ln1_b, netp);

    // 5) hidden = net @ fc1_w + fc1_b   (NO activation per source)
    gemm_kernel<true, false><<<dim3(DFF / 64, MROWS / 128), 256>>>(
        netp, fc1_w, fc1_b, nullptr, hidp, MROWS, DFF, DD);

    // 6) out = hidden @ fc2_w + fc2_b + net
    gemm_kernel<true, true><<<dim3(DD / 64, MROWS / 128), 256>>>(
        hidp, fc2_w, fc2_b, netp, out, MROWS, DD, DFF);
}

// round 15
// speedup vs baseline: 1.0041x; 1.0006x over previous
#include <cuda_runtime.h>
#include <cuda_bf16.h>
#include <cstddef>

// Problem constants
#define BB 2
#define NN 2048
#define DD 256
#define HH 8
#define HDD 32
#define DFF 1024
#define MROWS (BB*NN)          // 4096
static __device__ __constant__ float kScale = 5.656854249492381f; // sqrt(32), source MULTIPLIES

// ---------------- scratch (static device globals; no allocation) --------------
__device__ float g_qkv   [(size_t)BB*NN*3*DD];   // [B,N,768]
__device__ float g_att   [(size_t)BB*NN*DD];     // attention output (pre-proj)
__device__ float g_res   [(size_t)BB*NN*DD];     // proj + bias + x (pre-LN)
__device__ float g_net   [(size_t)BB*NN*DD];     // layernorm output
__device__ float g_hidden[(size_t)BB*NN*DFF];    // fc1 output

// ============================= GEMM =========================================
// C[M,N] = A[M,K] @ W[K,N]  (+ bias[N])  (+ res[M,N])
// Block tile 128x64, BK=32, 256 threads, 8x4 register micro-tile.
template<bool BIAS, bool RES>
__global__ __launch_bounds__(256) void gemm_kernel(
    const float* __restrict__ A, const float* __restrict__ W,
    const float* __restrict__ bias, const float* __restrict__ res,
    float* __restrict__ C, int M, int N, int K)
{
    constexpr int BM = 128, BN = 64, BK = 32;
    constexpr int PAD = 4;                       // bank-conflict mitigation for transposed store
    __shared__ float As[BK][BM + PAD];           // As[k][m]
    __shared__ float Bs[BK][BN];                 // Bs[k][n]

    const int tid = threadIdx.x;
    const int bm  = blockIdx.y;
    const int bn  = blockIdx.x;
    const int tx  = tid & 15;                    // 16 col-groups (TN=4)
    const int ty  = tid >> 4;                    // 16 row-groups (TM=8)

    float acc[8][4];
    #pragma unroll
    for (int i = 0; i < 8; i++)
        #pragma unroll
        for (int j = 0; j < 4; j++) acc[i][j] = 0.f;

    const int ar = tid >> 3;                     // 0..31 (A row within pass)
    const int ac = (tid & 7) * 4;                // 0..28 (A col, float4)
    const int br = tid >> 4;                     // 0..15 (B row within pass)
    const int bc = (tid & 15) * 4;               // 0..60 (B col, float4)

    const float* Ablk = A + (size_t)(bm * BM) * K;
    const float* Wblk = W + (size_t)bn * BN;

    for (int kt = 0; kt < K; kt += BK) {
        // ---- load A tile (128 x 32), store transposed ----
        #pragma unroll
        for (int p = 0; p < 4; p++) {
            int r = ar + p * 32;
            float4 v = *(const float4*)(Ablk + (size_t)r * K + kt + ac);
            As[ac + 0][r] = v.x; As[ac + 1][r] = v.y;
            As[ac + 2][r] = v.z; As[ac + 3][r] = v.w;
        }
        // ---- load B tile (32 x 64) ----
        #pragma unroll
        for (int p = 0; p < 2; p++) {
            int r = br + p * 16;
            *(float4*)&Bs[r][bc] = *(const float4*)(Wblk + (size_t)(kt + r) * N + bc);
        }
        __syncthreads();

        #pragma unroll
        for (int k = 0; k < BK; k++) {
            float4 b4 = *(const float4*)&Bs[k][tx * 4];
            float4 a0 = *(const float4*)&As[k][ty * 8];
            float4 a1 = *(const float4*)&As[k][ty * 8 + 4];
            float a[8] = {a0.x, a0.y, a0.z, a0.w, a1.x, a1.y, a1.z, a1.w};
            float bb[4] = {b4.x, b4.y, b4.z, b4.w};
            #pragma unroll
            for (int i = 0; i < 8; i++)
                #pragma unroll
                for (int j = 0; j < 4; j++)
                    acc[i][j] += a[i] * bb[j];
        }
        __syncthreads();
    }

    // ---- epilogue ----
    const int col = bn * BN + tx * 4;
    float4 bv = make_float4(0.f, 0.f, 0.f, 0.f);
    if (BIAS) bv = *(const float4*)(bias + col);
    #pragma unroll
    for (int i = 0; i < 8; i++) {
        int row = bm * BM + ty * 8 + i;
        float4 o;
        o.x = acc[i][0] + bv.x; o.y = acc[i][1] + bv.y;
        o.z = acc[i][2] + bv.z; o.w = acc[i][3] + bv.w;
        if (RES) {
            float4 r = *(const float4*)(res + (size_t)row * N + col);
            o.x += r.x; o.y += r.y; o.z += r.z; o.w += r.w;
        }
        *(float4*)(C + (size_t)row * N + col) = o;
    }
}

// ============================ Attention ======================================
// Flash-style, fp32. 1 thread = 1 query row. Block: 128 threads = 128 queries.
// Grid: (N/128, H, B). K/V tiles of 32 keys in shared memory.
__global__ __launch_bounds__(128) void attn_kernel(
    const float* __restrict__ qkv, float* __restrict__ out)
{
    const int tid  = threadIdx.x;
    const int h    = blockIdx.y;
    const int b    = blockIdx.z;
    const int qrow = blockIdx.x * 128 + tid;

    const float* base = qkv + (size_t)b * NN * (3 * DD) + h * HDD;
    const float* Kb = base + DD;        // k at offset 256 in last dim
    const float* Vb = base + 2 * DD;    // v at offset 512

    __shared__ float4 Ks[32][8];
    __shared__ float4 Vs[32][8];

    float q[32], acc[32];
    {
        const float* qp = base + (size_t)qrow * (3 * DD);
        const float sc = kScale;
        #pragma unroll
        for (int i = 0; i < 8; i++) {
            float4 t = *(const float4*)(qp + i * 4);
            q[4*i+0] = t.x * sc; q[4*i+1] = t.y * sc;
            q[4*i+2] = t.z * sc; q[4*i+3] = t.w * sc;
        }
    }
    #pragma unroll
    for (int d = 0; d < 32; d++) acc[d] = 0.f;
    float m = -1e30f, l = 0.f;

    const int r0 = tid >> 3,        c0 = (tid & 7) * 4;
    const int r1 = (tid + 128) >> 3, c1 = (tid & 7) * 4;   // second pass, rows 16..31

    for (int kb = 0; kb < NN; kb += 32) {
        // ---- load 32 keys + 32 values (each 32 floats) ----
        Ks[r0][c0 >> 2] = *(const float4*)(Kb + (size_t)(kb + r0) * (3 * DD) + c0);
        Ks[r1][c1 >> 2] = *(const float4*)(Kb + (size_t)(kb + r1) * (3 * DD) + c1);
        Vs[r0][c0 >> 2] = *(const float4*)(Vb + (size_t)(kb + r0) * (3 * DD) + c0);
        Vs[r1][c1 >> 2] = *(const float4*)(Vb + (size_t)(kb + r1) * (3 * DD) + c1);
        __syncthreads();

        // ---- scores: s[j] = (q*scale) . k_j ----
        float s[32];
        #pragma unroll
        for (int j = 0; j < 32; j++) {
            float a0 = 0.f, a1 = 0.f, a2 = 0.f, a3 = 0.f;
            #pragma unroll
            for (int i = 0; i < 8; i++) {
                float4 kv = Ks[j][i];
                a0 += q[4*i+0] * kv.x; a1 += q[4*i+1] * kv.y;
                a2 += q[4*i+2] * kv.z; a3 += q[4*i+3] * kv.w;
            }
            s[j] = (a0 + a1) + (a2 + a3);
        }

        // ---- online softmax, rescale once per tile ----
        float tmax = s[0];
        #pragma unroll
        for (int j = 1; j < 32; j++) tmax = fmaxf(tmax, s[j]);
        float mnew  = fmaxf(m, tmax);
        float alpha = __expf(m - mnew);
        l *= alpha;
        #pragma unroll
        for (int d = 0; d < 32; d++) acc[d] *= alpha;

        #pragma unroll
        for (int j = 0; j < 32; j++) {
            float p = __expf(s[j] - mnew);
            l += p;
            #pragma unroll
            for (int i = 0; i < 8; i++) {
                float4 vv = Vs[j][i];
                acc[4*i+0] += p * vv.x; acc[4*i+1] += p * vv.y;
                acc[4*i+2] += p * vv.z; acc[4*i+3] += p * vv.w;
            }
        }
        m = mnew;
        __syncthreads();
    }

    const float inv = 1.f / l;
    float* op = out + ((size_t)(b * NN + qrow)) * DD + h * HDD;
    #pragma unroll
    for (int i = 0; i < 8; i++) {
        float4 o;
        o.x = acc[4*i+0] * inv; o.y = acc[4*i+1] * inv;
        o.z = acc[4*i+2] * inv; o.w = acc[4*i+3] * inv;
        *(float4*)(op + 4 * i) = o;
    }
}

// ============================ LayerNorm ======================================
// One block per row (D=256), 256 threads.
__global__ __launch_bounds__(256) void ln_kernel(
    const float* __restrict__ in, const float* __restrict__ gamma,
    const float* __restrict__ beta, float* __restrict__ out)
{
    __shared__ float red[8];
    const int row = blockIdx.x;
    const int tid = threadIdx.x;

    float v = in[(size_t)row * DD + tid];

    float s = v;
    #pragma unroll
    for (int o = 16; o; o >>= 1) s += __shfl_xor_sync(0xffffffffu, s, o);
    if ((tid & 31) == 0) red[tid >> 5] = s;
    __syncthreads();
    float tot = 0.f;
    #pragma unroll
    for (int i = 0; i < 8; i++) tot += red[i];
    const float mu = tot * (1.f / DD);

    float d = v - mu;
    float sq = d * d;
    #pragma unroll
    for (int o = 16; o; o >>= 1) sq += __shfl_xor_sync(0xffffffffu, sq, o);
    __syncthreads();
    if ((tid & 31) == 0) red[tid >> 5] = sq;
    __syncthreads();
    float var = 0.f;
    #pragma unroll
    for (int i = 0; i < 8; i++) var += red[i];
    var *= (1.f / DD);

    out[(size_t)row * DD + tid] = d * rsqrtf(var + 1e-5f) * gamma[tid] + beta[tid];
}

// ============================ launch =========================================
extern "C" void kernel_launch(void* const* d_in, const int* in_sizes, int n_in,
                              void* d_out, int out_size)
{
    const float* x      = (const float*)d_in[0];
    const float* qkv_w  = (const float*)d_in[1];
    const float* proj_w = (const float*)d_in[2];
    const float* proj_b = (const float*)d_in[3];
    const float* fc1_w  = (const float*)d_in[4];
    const float* fc1_b  = (const float*)d_in[5];
    const float* fc2_w  = (const float*)d_in[6];
    const float* fc2_b  = (const float*)d_in[7];
    const float* ln1_g  = (const float*)d_in[8];
    const float* ln1_b  = (const float*)d_in[9];
    float* out = (float*)d_out;

    float *qkvp, *attp, *resp, *netp, *hidp;
    cudaGetSymbolAddress((void**)&qkvp, g_qkv);
    cudaGetSymbolAddress((void**)&attp, g_att);
    cudaGetSymbolAddress((void**)&resp, g_res);
    cudaGetSymbolAddress((void**)&netp, g_net);
    cudaGetSymbolAddress((void**)&hidp, g_hidden);

    // 1) qkv = x @ qkv_w               [4096,768] = [4096,256]@[256,768]
    gemm_kernel<false, false><<<dim3(768 / 64, MROWS / 128), 256>>>(
        x, qkv_w, nullptr, nullptr, qkvp, MROWS, 3 * DD, DD);

    // 2) attention (fused flash, per head)
    attn_kernel<<<dim3(NN / 128, HH, BB), 128>>>(qkvp, attp);

    // 3) res = att @ proj_w + proj_b + x
    gemm_kernel<true, true><<<dim3(DD / 64, MROWS / 128), 256>>>(
        attp, proj_w, proj_b, x, resp, MROWS, DD, DD);

    // 4) net = layernorm(res)
    ln_kernel<<<MROWS, 256>>>(resp, ln1_g, ln1_b, netp);

    // 5) hidden = net @ fc1_w + fc1_b   (NO activation per source)
    gemm_kernel<true, false><<<dim3(DFF / 64, MROWS / 128), 256>>>(
        netp, fc1_w, fc1_b, nullptr, hidp, MROWS, DFF, DD);

    // 6) out = hidden @ fc2_w + fc2_b + net
    gemm_kernel<true, true><<<dim3(DD / 64, MROWS / 128), 256>>>(
        hidp, fc2_w, fc2_b, netp, out, MROWS, DD, DFF);
}